// round 17
// baseline (speedup 1.0000x reference)
#include <cuda_runtime.h>
#include <cuda_bf16.h>

#define NSP 8192
#define NR  2097152
#define NCTA 148
#define NTHR 1024
#define RCHUNK 37          // 148 = 4 * 37

__device__ float g_partial[NCTA * NSP];   // 4.85 MB static scratch, overwritten each call

__device__ __forceinline__ float ex2_approx(float x) {
    float y;
    asm("ex2.approx.ftz.f32 %0, %1;" : "=f"(y) : "f"(x));
    return y;
}

__device__ __forceinline__ void red_shared_add(float* p, float v) {
    asm volatile("red.shared.add.f32 [%0], %1;"
                 :: "l"(__cvta_generic_to_shared(p)), "f"(v) : "memory");
}

struct Rxn {
    float a, b, g;
    int   t;
    int2  sp;
    int4  rw;
};

__device__ __forceinline__ Rxn load_rxn(
    int r,
    const float* __restrict__ alpha, const float* __restrict__ beta,
    const float* __restrict__ gamma, const int* __restrict__ rtype,
    const int2* __restrict__ rspec,  const int4* __restrict__ rows4)
{
    Rxn x;
    x.a = alpha[r]; x.b = beta[r]; x.g = gamma[r];
    x.t = rtype[r]; x.sp = rspec[r]; x.rw = rows4[r];
    return x;
}

__global__ __launch_bounds__(NTHR, 1)
void rates_scatter_kernel(
    const float* __restrict__ abund,
    const float* __restrict__ Tptr,
    const float* __restrict__ crptr,
    const float* __restrict__ fuvptr,
    const float* __restrict__ alpha,
    const float* __restrict__ beta,
    const float* __restrict__ gamma,
    const int*   __restrict__ rtype,
    const int2*  __restrict__ rspec,
    const int4*  __restrict__ rows4,
    float* __restrict__ out)
{
    extern __shared__ float smem[];
    float* acc = smem;          // [NSP] per-CTA accumulator (REDS targets)
    float* sab = smem + NSP;    // [NSP] staged abundances

    const int tid = threadIdx.x;
    // Vectorized init: 2 float4 iterations each.
    {
        const float4* a4 = (const float4*)abund;
        float4* s4 = (float4*)sab;
        float4* c4 = (float4*)acc;
        const float4 z = make_float4(0.f, 0.f, 0.f, 0.f);
        #pragma unroll
        for (int i = tid; i < NSP / 4; i += NTHR) {
            s4[i] = a4[i];
            c4[i] = z;
        }
    }
    // Zero poisoned output (reduce runs strictly after this kernel).
    if (blockIdx.x == NCTA - 1) {
        float4* o4 = (float4*)out;
        const float4 z = make_float4(0.f, 0.f, 0.f, 0.f);
        for (int i = tid; i < NSP / 4; i += NTHR) o4[i] = z;
    }
    __syncthreads();

    const float T   = *Tptr;
    const float cr  = *crptr;
    const float fuv = *fuvptr;
    const float L2E = 1.4426950408889634f;           // log2(e)
    const float c1  = __log2f(T * (1.0f / 300.0f));  // log2(T/300)
    const float c2  = -L2E / T;                      // exp(-g/T) = exp2(g*c2)

    const int stride = NCTA * NTHR;                  // 151552
    int r = blockIdx.x * NTHR + tid;

    // Depth-2 software pipeline: loads for i+1 and i+2 stay in flight.
    Rxn cur, n1;
    if (r < NR)          cur = load_rxn(r,          alpha, beta, gamma, rtype, rspec, rows4);
    if (r + stride < NR) n1  = load_rxn(r + stride, alpha, beta, gamma, rtype, rspec, rows4);

    while (r < NR) {
        const int r2 = r + 2 * stride;

        Rxn n2;
        if (r2 < NR) n2 = load_rxn(r2, alpha, beta, gamma, rtype, rspec, rows4);

        {
            const float e  = (cur.t == 0) ? fmaf(cur.b, c1, cur.g * c2)
                                          : (-cur.g * L2E);
            const float ex = ex2_approx(e);
            float k;
            if (cur.t == 1)      k = cur.a * cr;
            else if (cur.t == 2) k = cur.a * fuv * ex;
            else                 k = cur.a * ex;

            k *= sab[cur.sp.x] * sab[cur.sp.y];

            red_shared_add(&acc[cur.rw.x], -k);   // no-return REDS
            red_shared_add(&acc[cur.rw.y], -k);
            red_shared_add(&acc[cur.rw.z],  k);
            red_shared_add(&acc[cur.rw.w],  k);
        }

        cur = n1;
        n1  = n2;
        r  += stride;
    }

    __syncthreads();
    // Vectorized coalesced STG flush: 2 x STG.128 per thread.
    {
        float4* mine4 = (float4*)(g_partial + (size_t)blockIdx.x * NSP);
        const float4* acc4 = (const float4*)acc;
        #pragma unroll
        for (int i = tid; i < NSP / 4; i += NTHR)
            mine4[i] = acc4[i];
    }
}

// Reduce over 148 partials, float4-wide: grid (8, 4), 256 threads.
// Thread owns 4 species (one float4); sums rows [37*by, 37*(by+1)) with
// 4-deep MLP, then 4 no-return REDG (4 per address across y-slices).
__global__ __launch_bounds__(256, 8)
void reduce_kernel(float* __restrict__ out) {
    const int q  = blockIdx.x * blockDim.x + threadIdx.x;   // float4 index [0, 2048)
    const int c0 = blockIdx.y * RCHUNK;
    const float4* p = (const float4*)(g_partial + (size_t)c0 * NSP) + q;
    const int step = NSP / 4;

    float sx = 0.f, sy = 0.f, sz = 0.f, sw = 0.f;
    #pragma unroll 4
    for (int c = 0; c < RCHUNK; c++) {
        const float4 v = p[(size_t)c * step];
        sx += v.x; sy += v.y; sz += v.z; sw += v.w;
    }

    float* o = out + 4 * q;
    atomicAdd(o + 0, sx);    // no-return REDG, 4 per address
    atomicAdd(o + 1, sy);
    atomicAdd(o + 2, sz);
    atomicAdd(o + 3, sw);
}

extern "C" void kernel_launch(void* const* d_in, const int* in_sizes, int n_in,
                              void* d_out, int out_size) {
    const float* abund  = (const float*)d_in[0];
    const float* T      = (const float*)d_in[1];
    const float* crr    = (const float*)d_in[2];
    const float* fuvr   = (const float*)d_in[3];
    float* out = (float*)d_out;

    const int smem_bytes = 2 * NSP * sizeof(float);  // 64 KB
    cudaFuncSetAttribute(rates_scatter_kernel,
                         cudaFuncAttributeMaxDynamicSharedMemorySize, smem_bytes);

    rates_scatter_kernel<<<NCTA, NTHR, smem_bytes>>>(
        abund, T, crr, fuvr,
        (const float*)d_in[4], (const float*)d_in[5], (const float*)d_in[6],
        (const int*)d_in[7], (const int2*)d_in[8], (const int4*)d_in[9],
        out);

    reduce_kernel<<<dim3(8, 4), 256>>>(out);
}